// round 1
// baseline (speedup 1.0000x reference)
#include <cuda_runtime.h>
#include <math.h>

#define BB 32
#define LL 2048
#define HH 8
#define DMET 16
#define SDIM 27
#define DM 256
#define NLAYERS 4
#define DS 64
#define TE 256
#define LT 2055          // LL + HH - 1
#define LTP 2056         // padded row stride (16B aligned rows)
#define FIN 44           // DMET + 1 + SDIM

// ---------------- scratch (device globals; no allocation) ----------------
__device__ float g_h[(size_t)BB * DM * LTP];   // activations  [b][d][l]
__device__ float g_y[(size_t)BB * DM * LTP];   // ssm pre-gelu  [b][d][l]
__device__ float g_tb[BB * DM];
__device__ float g_ar[DM * DS], g_ai[DM * DS], g_ckr[DM * DS], g_cki[DM * DS];
__device__ float g_mean[DM], g_rstd[DM];

// ---------------- helpers ----------------
__device__ __forceinline__ float sigm(float x) { return 1.f / (1.f + __expf(-x)); }
__device__ __forceinline__ float gelu_tanh(float v) {
    // jax.nn.gelu approximate=True: 0.5 v (1 + tanh(sqrt(2/pi)(v + 0.044715 v^3)))
    //                             = v * sigmoid(2*sqrt(2/pi)*(v + 0.044715 v^3))
    float v3 = v * v * v;
    float w = 1.5957691216057308f * fmaf(0.044715f, v3, v);
    return v * sigm(w);
}

// ---------------- time MLP: t_b[b,d] ----------------
__global__ void k_timemlp(const float* __restrict__ t, const float* __restrict__ freqs,
                          const float* __restrict__ phases,
                          const float* __restrict__ W1, const float* __restrict__ b1,
                          const float* __restrict__ W2, const float* __restrict__ b2) {
    int b = blockIdx.x, tid = threadIdx.x;
    __shared__ float tf[TE];
    __shared__ float hid[2 * TE];
    float tv = t[b];
    tf[tid] = cosf(fmaf(tv, freqs[tid], phases[tid])) * 1.41421356237309515f;
    __syncthreads();
    for (int j = tid; j < 2 * TE; j += 256) {
        float acc = b1[j];
        #pragma unroll 8
        for (int k = 0; k < TE; ++k) acc = fmaf(tf[k], W1[k * 512 + j], acc);
        hid[j] = acc * sigm(acc);
    }
    __syncthreads();
    float acc = b2[tid];
    #pragma unroll 8
    for (int k = 0; k < 2 * TE; ++k) acc = fmaf(hid[k], W2[k * 256 + tid], acc);
    g_tb[b * DM + tid] = acc;
}

// ---------------- input projection + feature fusion ----------------
__global__ void k_inproj(const float* __restrict__ xp, const float* __restrict__ noisy,
                         const float* __restrict__ xf, const float* __restrict__ sa,
                         const float* __restrict__ inW, const float* __restrict__ inb) {
    int b = blockIdx.z, dt = blockIdx.y, ltile = blockIdx.x;
    int tid = threadIdx.x;
    int ll = tid & 31, dl = tid >> 5;      // 8 d x 32 l per block
    int l0 = ltile * 32, d0 = dt * 8;
    __shared__ float sf[32][45];
    __shared__ float sw[FIN][8];
    for (int i = tid; i < 32 * FIN; i += 256) {
        int li = i / FIN, f = i % FIN;
        int l = l0 + li;
        float v = 0.f;
        if (l < LT) {
            if (f < DMET)
                v = (l < LL) ? xp[((size_t)b * LL + l) * DMET + f]
                             : xf[((size_t)b * (HH - 1) + (l - LL)) * DMET + f];
            else if (f == DMET)
                v = (l >= LL - 1) ? noisy[b * HH + (l - (LL - 1))] : 0.f;
            else
                v = sa[b * SDIM + (f - DMET - 1)];
        }
        sf[li][f] = v;
    }
    for (int i = tid; i < FIN * 8; i += 256) {
        int f = i >> 3, c = i & 7;
        sw[f][c] = inW[f * DM + d0 + c];
    }
    __syncthreads();
    int l = l0 + ll, d = d0 + dl;
    float acc = inb[d];
    #pragma unroll
    for (int f = 0; f < FIN; ++f) acc = fmaf(sf[ll][f], sw[f][dl], acc);
    if (l >= LL - 1) acc += g_tb[b * DM + d];
    if (l < LT) g_h[((size_t)b * DM + d) * LTP + l] = acc;
}

// ---------------- per-layer discretization ----------------
__global__ void k_disc(const float* __restrict__ log_dt, const float* __restrict__ Are,
                       const float* __restrict__ Aim, const float* __restrict__ Cre,
                       const float* __restrict__ Cim) {
    int idx = blockIdx.x * 256 + threadIdx.x;   // < DM*DS
    int d = idx >> 6;
    float dt = expf(log_dt[d]);
    float ar_ = Are[idx], ai_ = Aim[idx];
    float xr = dt * ar_, xi = dt * ai_;
    float mag = expf(xr);
    float cs = cosf(xi), sn = sinf(xi);
    float a_r = mag * cs, a_i = mag * sn;
    // expm1(dtA): e^{xr}cos(xi)-1 = expm1(xr)*cos + (cos-1);  imag = e^{xr} sin
    float em = expm1f(xr);
    float er = fmaf(em, cs, cs - 1.f);
    float ei = a_i;
    float inv = 1.f / fmaf(ar_, ar_, ai_ * ai_);
    float qr = fmaf(er, ar_, ei * ai_) * inv;
    float qi = fmaf(ei, ar_, -er * ai_) * inv;
    float cr = Cre[idx], ci = Cim[idx];
    g_ckr[idx] = 2.f * fmaf(cr, qr, -ci * qi);
    g_cki[idx] = 2.f * fmaf(cr, qi, ci * qr);
    g_ar[idx] = a_r;
    g_ai[idx] = a_i;
}

// ---------------- SSM recurrent scan: warp per (b,d) ----------------
__global__ void __launch_bounds__(256) k_scan(const float* __restrict__ Dv) {
    int wid = (blockIdx.x * blockDim.x + threadIdx.x) >> 5;  // 0..8191
    int lane = threadIdx.x & 31;
    int b = wid >> 8, d = wid & 255;
    const float* u = g_h + ((size_t)b * DM + d) * LTP;
    float* yo = g_y + ((size_t)b * DM + d) * LTP;
    int i0 = d * DS + lane, i1 = i0 + 32;
    float a0r = g_ar[i0], a0i = g_ai[i0], c0r = g_ckr[i0], c0i = g_cki[i0];
    float a1r = g_ar[i1], a1i = g_ai[i1], c1r = g_ckr[i1], c1i = g_cki[i1];
    float na0i = -a0i, na1i = -a1i, nc0i = -c0i, nc1i = -c1i;
    float Dd = Dv[d];
    float s0r = 0.f, s0i = 0.f, s1r = 0.f, s1i = 0.f;
    float yreg = 0.f;
    #pragma unroll 4
    for (int l = 0; l < LT; ++l) {
        float uv = __ldg(u + l);
        float n0r = fmaf(na0i, s0i, fmaf(a0r, s0r, uv));
        float n0i = fmaf(a0i, s0r, a0r * s0i);
        float n1r = fmaf(na1i, s1i, fmaf(a1r, s1r, uv));
        float n1i = fmaf(a1i, s1r, a1r * s1i);
        s0r = n0r; s0i = n0i; s1r = n1r; s1i = n1i;
        float p = fmaf(c0r, s0r, nc0i * s0i) + fmaf(c1r, s1r, nc1i * s1i);
        #pragma unroll
        for (int o = 16; o; o >>= 1) p += __shfl_xor_sync(0xffffffffu, p, o);
        float v = fmaf(Dd, uv, p);          // pre-gelu (gelu fused in GEMM load)
        if ((l & 31) == lane) yreg = v;
        if ((l & 31) == 31) yo[(l & ~31) + lane] = yreg;   // coalesced 128B store
    }
    if (lane < (LT & 31)) yo[(LT & ~31) + lane] = yreg;
}

// ---------------- out-projection GEMM + GLU + residual (writes pre-BN into g_h) -------
__global__ void __launch_bounds__(256) k_gemm(const float* __restrict__ W,
                                              const float* __restrict__ ob) {
    const int b = blockIdx.z, dt = blockIdx.y, lt = blockIdx.x;
    const int tid = threadIdx.x;
    const int lr = tid & 15, dr = tid >> 4;
    const int d0 = dt * 64, l0 = lt * 64;
    __shared__ float As1[16][64];
    __shared__ float As2[16][64];
    __shared__ float Bs[16][64];
    float ac1[4][4] = {{0.f}}, ac2[4][4] = {{0.f}};
    const float* Yb = g_y + (size_t)b * DM * LTP;
    for (int kt = 0; kt < 16; ++kt) {
        int k0 = kt * 16;
        __syncthreads();
        #pragma unroll
        for (int r = 0; r < 4; ++r) {
            int idx = tid + r * 256;
            int f = idx >> 6, c = idx & 63;
            As1[f][c] = W[(k0 + f) * 512 + d0 + c];
            As2[f][c] = W[(k0 + f) * 512 + 256 + d0 + c];
            int l = l0 + c;
            float v = (l < LT) ? Yb[(size_t)(k0 + f) * LTP + l] : 0.f;
            Bs[f][c] = gelu_tanh(v);
        }
        __syncthreads();
        #pragma unroll
        for (int kk = 0; kk < 16; ++kk) {
            float a1[4], a2[4], bv[4];
            #pragma unroll
            for (int j = 0; j < 4; ++j) {
                a1[j] = As1[kk][dr * 4 + j];
                a2[j] = As2[kk][dr * 4 + j];
                bv[j] = Bs[kk][lr * 4 + j];
            }
            #pragma unroll
            for (int j = 0; j < 4; ++j)
                #pragma unroll
                for (int m = 0; m < 4; ++m) {
                    ac1[j][m] = fmaf(a1[j], bv[m], ac1[j][m]);
                    ac2[j][m] = fmaf(a2[j], bv[m], ac2[j][m]);
                }
        }
    }
    float* Hb = g_h + (size_t)b * DM * LTP;
    #pragma unroll
    for (int j = 0; j < 4; ++j) {
        int d = d0 + dr * 4 + j;
        float bz1 = ob[d], bz2 = ob[256 + d];
        #pragma unroll
        for (int m = 0; m < 4; ++m) {
            int l = l0 + lr * 4 + m;
            if (l < LT) {
                float z1 = ac1[j][m] + bz1, z2 = ac2[j][m] + bz2;
                float g = z1 * sigm(z2);
                size_t off = (size_t)d * LTP + l;
                Hb[off] = Hb[off] + g;
            }
        }
    }
}

// ---------------- BatchNorm (training-mode batch stats) ----------------
__global__ void k_bnstats() {
    int d = blockIdx.x, tid = threadIdx.x;
    float s = 0.f, s2 = 0.f;
    for (int b = 0; b < BB; ++b) {
        const float* row = g_h + ((size_t)b * DM + d) * LTP;
        for (int l = tid; l < LT; l += 256) {
            float v = row[l];
            s += v;
            s2 = fmaf(v, v, s2);
        }
    }
    __shared__ float sh1[256], sh2[256];
    sh1[tid] = s; sh2[tid] = s2;
    __syncthreads();
    for (int o = 128; o; o >>= 1) {
        if (tid < o) { sh1[tid] += sh1[tid + o]; sh2[tid] += sh2[tid + o]; }
        __syncthreads();
    }
    if (tid == 0) {
        float n = (float)(BB * LT);
        float mean = sh1[0] / n;
        float var = sh2[0] / n - mean * mean;
        g_mean[d] = mean;
        g_rstd[d] = rsqrtf(var + 1e-5f);
    }
}

__global__ void k_bnapply(const float* __restrict__ gamma, const float* __restrict__ beta) {
    int row = blockIdx.y;
    int l = blockIdx.x * 256 + threadIdx.x;
    if (l >= LT) return;
    int d = row & (DM - 1);
    float sc = g_rstd[d] * gamma[d];
    float m = g_mean[d], bt = beta[d];
    size_t off = (size_t)row * LTP + l;
    g_h[off] = fmaf(g_h[off] - m, sc, bt);
}

// ---------------- head over last H positions ----------------
__global__ void k_head(const float* __restrict__ W1, const float* __restrict__ b1,
                       const float* __restrict__ W2, const float* __restrict__ b2,
                       float* __restrict__ out) {
    int i = blockIdx.x, b = blockIdx.y, tid = threadIdx.x;  // 128 threads
    int l = (LL - 1) + i;
    float acc = b1[tid];
    const float* Hb = g_h + (size_t)b * DM * LTP + l;
    #pragma unroll 4
    for (int d = 0; d < DM; ++d) acc = fmaf(Hb[(size_t)d * LTP], W1[d * 128 + tid], acc);
    float sv = acc * sigm(acc);
    __shared__ float sh[128];
    sh[tid] = sv * W2[tid];
    __syncthreads();
    for (int o = 64; o; o >>= 1) {
        if (tid < o) sh[tid] += sh[tid + o];
        __syncthreads();
    }
    if (tid == 0) out[b * HH + i] = sh[0] + b2[0];
}

// ---------------- launch ----------------
extern "C" void kernel_launch(void* const* d_in, const int* in_sizes, int n_in,
                              void* d_out, int out_size) {
    const float* x_past   = (const float*)d_in[0];
    const float* noisy    = (const float*)d_in[1];
    const float* t        = (const float*)d_in[2];
    const float* x_future = (const float*)d_in[3];
    const float* stat     = (const float*)d_in[4];
    const float* freqs    = (const float*)d_in[5];
    const float* phases   = (const float*)d_in[6];
    const float* in_W     = (const float*)d_in[7];
    const float* in_b     = (const float*)d_in[8];
    const float* tm_W1    = (const float*)d_in[9];
    const float* tm_b1    = (const float*)d_in[10];
    const float* tm_W2    = (const float*)d_in[11];
    const float* tm_b2    = (const float*)d_in[12];
    const float* log_dt   = (const float*)d_in[13];
    const float* A_re     = (const float*)d_in[14];
    const float* A_im     = (const float*)d_in[15];
    const float* C_re     = (const float*)d_in[16];
    const float* C_im     = (const float*)d_in[17];
    const float* Dv       = (const float*)d_in[18];
    const float* out_W    = (const float*)d_in[19];
    const float* out_b    = (const float*)d_in[20];
    const float* bn_g     = (const float*)d_in[21];
    const float* bn_b     = (const float*)d_in[22];
    const float* hW1      = (const float*)d_in[23];
    const float* hb1      = (const float*)d_in[24];
    const float* hW2      = (const float*)d_in[25];
    const float* hb2      = (const float*)d_in[26];
    float* out = (float*)d_out;

    k_timemlp<<<BB, 256>>>(t, freqs, phases, tm_W1, tm_b1, tm_W2, tm_b2);
    k_inproj<<<dim3(65, DM / 8, BB), 256>>>(x_past, noisy, x_future, stat, in_W, in_b);

    for (int i = 0; i < NLAYERS; ++i) {
        k_disc<<<DM * DS / 256, 256>>>(log_dt + i * DM, A_re + (size_t)i * DM * DS,
                                       A_im + (size_t)i * DM * DS, C_re + (size_t)i * DM * DS,
                                       C_im + (size_t)i * DM * DS);
        k_scan<<<(BB * DM) / 8, 256>>>(Dv + i * DM);
        k_gemm<<<dim3(33, 4, BB), 256>>>(out_W + (size_t)i * DM * 2 * DM, out_b + i * 2 * DM);
        k_bnstats<<<DM, 256>>>();
        k_bnapply<<<dim3((LT + 255) / 256, BB * DM), 256>>>(bn_g + i * DM, bn_b + i * DM);
    }
    k_head<<<dim3(HH, BB), 128>>>(hW1, hb1, hW2, hb2, out);
}

// round 3
// speedup vs baseline: 1.7431x; 1.7431x over previous
#include <cuda_runtime.h>
#include <math.h>

#define BB 32
#define LL 2048
#define HH 8
#define DMET 16
#define SDIM 27
#define DM 256
#define NLAYERS 4
#define DS 64
#define TE 256
#define LT 2055          // LL + HH - 1
#define LTP 2056         // padded row stride
#define FIN 44           // DMET + 1 + SDIM
#define NT 1056          // 33 l-tiles * 32 batches (BN partial slots)

typedef unsigned long long ull;

// ---------------- scratch (device globals; no allocation) ----------------
__device__ float g_h[(size_t)BB * DM * LTP];   // activations (pre-BN) [b][d][l]
__device__ float g_y[(size_t)BB * DM * LTP];   // gelu(ssm out)        [b][d][l]
__device__ float g_tb[BB * DM];
__device__ float g_ar[DM * DS], g_ai[DM * DS], g_ckr[DM * DS], g_cki[DM * DS];
__device__ float g_mean[DM], g_rstd[DM];
__device__ float g_bnp0[DM * NT], g_bnp1[DM * NT];

// ---------------- f32x2 packed math ----------------
__device__ __forceinline__ ull pk2(float a, float b) {
    ull r; asm("mov.b64 %0,{%1,%2};" : "=l"(r) : "f"(a), "f"(b)); return r;
}
__device__ __forceinline__ void up2(ull v, float& a, float& b) {
    asm("mov.b64 {%0,%1},%2;" : "=f"(a), "=f"(b) : "l"(v));
}
__device__ __forceinline__ ull f2fma(ull a, ull b, ull c) {
    ull d; asm("fma.rn.f32x2 %0,%1,%2,%3;" : "=l"(d) : "l"(a), "l"(b), "l"(c)); return d;
}
__device__ __forceinline__ ull f2mul(ull a, ull b) {
    ull d; asm("mul.rn.f32x2 %0,%1,%2;" : "=l"(d) : "l"(a), "l"(b)); return d;
}

// ---------------- helpers ----------------
__device__ __forceinline__ float sigm(float x) { return 1.f / (1.f + __expf(-x)); }
__device__ __forceinline__ float gelu_tanh(float v) {
    float v3 = v * v * v;
    float w = 1.5957691216057308f * fmaf(0.044715f, v3, v);
    return v * sigm(w);
}

// ---------------- time MLP ----------------
__global__ void k_timemlp(const float* __restrict__ t, const float* __restrict__ freqs,
                          const float* __restrict__ phases,
                          const float* __restrict__ W1, const float* __restrict__ b1,
                          const float* __restrict__ W2, const float* __restrict__ b2) {
    int b = blockIdx.x, tid = threadIdx.x;
    __shared__ float tf[TE];
    __shared__ float hid[2 * TE];
    float tv = t[b];
    tf[tid] = cosf(fmaf(tv, freqs[tid], phases[tid])) * 1.41421356237309515f;
    __syncthreads();
    for (int j = tid; j < 2 * TE; j += 256) {
        float acc = b1[j];
        #pragma unroll 8
        for (int k = 0; k < TE; ++k) acc = fmaf(tf[k], W1[k * 512 + j], acc);
        hid[j] = acc * sigm(acc);
    }
    __syncthreads();
    float acc = b2[tid];
    #pragma unroll 8
    for (int k = 0; k < 2 * TE; ++k) acc = fmaf(hid[k], W2[k * 256 + tid], acc);
    g_tb[b * DM + tid] = acc;
}

// ---------------- input projection ----------------
__global__ void k_inproj(const float* __restrict__ xp, const float* __restrict__ noisy,
                         const float* __restrict__ xf, const float* __restrict__ sa,
                         const float* __restrict__ inW, const float* __restrict__ inb) {
    int b = blockIdx.z, dt = blockIdx.y, ltile = blockIdx.x;
    int tid = threadIdx.x;
    int ll = tid & 31, dl = tid >> 5;
    int l0 = ltile * 32, d0 = dt * 8;
    __shared__ float sf[32][45];
    __shared__ float sw[FIN][8];
    for (int i = tid; i < 32 * FIN; i += 256) {
        int li = i / FIN, f = i % FIN;
        int l = l0 + li;
        float v = 0.f;
        if (l < LT) {
            if (f < DMET)
                v = (l < LL) ? xp[((size_t)b * LL + l) * DMET + f]
                             : xf[((size_t)b * (HH - 1) + (l - LL)) * DMET + f];
            else if (f == DMET)
                v = (l >= LL - 1) ? noisy[b * HH + (l - (LL - 1))] : 0.f;
            else
                v = sa[b * SDIM + (f - DMET - 1)];
        }
        sf[li][f] = v;
    }
    for (int i = tid; i < FIN * 8; i += 256) {
        int f = i >> 3, c = i & 7;
        sw[f][c] = inW[f * DM + d0 + c];
    }
    __syncthreads();
    int l = l0 + ll, d = d0 + dl;
    float acc = inb[d];
    #pragma unroll
    for (int f = 0; f < FIN; ++f) acc = fmaf(sf[ll][f], sw[f][dl], acc);
    if (l >= LL - 1) acc += g_tb[b * DM + d];
    if (l < LT) g_h[((size_t)b * DM + d) * LTP + l] = acc;
}

// ---------------- per-layer discretization ----------------
__global__ void k_disc(const float* __restrict__ log_dt, const float* __restrict__ Are,
                       const float* __restrict__ Aim, const float* __restrict__ Cre,
                       const float* __restrict__ Cim) {
    int idx = blockIdx.x * 256 + threadIdx.x;
    int d = idx >> 6;
    float dt = expf(log_dt[d]);
    float ar_ = Are[idx], ai_ = Aim[idx];
    float xr = dt * ar_, xi = dt * ai_;
    float mag = expf(xr);
    float cs = cosf(xi), sn = sinf(xi);
    float a_r = mag * cs, a_i = mag * sn;
    float em = expm1f(xr);
    float er = fmaf(em, cs, cs - 1.f);
    float ei = a_i;
    float inv = 1.f / fmaf(ar_, ar_, ai_ * ai_);
    float qr = fmaf(er, ar_, ei * ai_) * inv;
    float qi = fmaf(ei, ar_, -er * ai_) * inv;
    float cr = Cre[idx], ci = Cim[idx];
    g_ckr[idx] = 2.f * fmaf(cr, qr, -ci * qi);
    g_cki[idx] = 2.f * fmaf(cr, qi, ci * qr);
    g_ar[idx] = a_r;
    g_ai[idx] = a_i;
}

// ---------------- SSM scan: warp per (b,d), f32x2 states, smem transpose reduce ------
__global__ void __launch_bounds__(256) k_scan(const float* __restrict__ Dv,
                                              const float* __restrict__ pg,
                                              const float* __restrict__ pb,
                                              int apply_bn) {
    __shared__ float sp[8][32][33];
    int warp = threadIdx.x >> 5, lane = threadIdx.x & 31;
    int wid = blockIdx.x * 8 + warp;
    int b = wid >> 8, d = wid & 255;
    float mean = 0.f, scl = 1.f, bet = 0.f;
    if (apply_bn) { mean = g_mean[d]; scl = g_rstd[d] * pg[d]; bet = pb[d]; }
    int i0 = d * DS + lane, i1 = i0 + 32;
    ull ar2  = pk2(g_ar[i0],  g_ar[i1]);
    ull ai2  = pk2(g_ai[i0],  g_ai[i1]);
    ull nai2 = pk2(-g_ai[i0], -g_ai[i1]);
    ull cr2  = pk2(g_ckr[i0], g_ckr[i1]);
    ull nci2 = pk2(-g_cki[i0], -g_cki[i1]);
    ull sr2 = 0ull, si2 = 0ull;
    float Dd = Dv[d];
    const float* u = g_h + ((size_t)b * DM + d) * LTP;
    float* yo = g_y + ((size_t)b * DM + d) * LTP;

    for (int l0 = 0; l0 < 2048; l0 += 32) {
        float rv = u[l0 + lane];
        rv = fmaf(rv - mean, scl, bet);
        #pragma unroll
        for (int j = 0; j < 32; ++j) {
            float uv = __shfl_sync(0xffffffffu, rv, j);
            ull uv2 = pk2(uv, uv);
            ull t   = f2fma(nai2, si2, uv2);
            ull nsr = f2fma(ar2, sr2, t);
            ull nsi = f2fma(ai2, sr2, f2mul(ar2, si2));
            sr2 = nsr; si2 = nsi;
            ull pr = f2fma(cr2, sr2, f2mul(nci2, si2));
            float px, py; up2(pr, px, py);
            sp[warp][j][lane] = px + py;   // [step][owner]
        }
        __syncwarp();
        // output position = lane: sum over the 32 owners (row read, conflict-free)
        float cs = 0.f;
        #pragma unroll
        for (int j = 0; j < 32; ++j) cs += sp[warp][lane][j];
        yo[l0 + lane] = gelu_tanh(fmaf(Dd, rv, cs));
        __syncwarp();
    }
    // tail: 7 steps
    {
        const int l0 = 2048;
        float rv = (lane < 7) ? fmaf(u[l0 + lane] - mean, scl, bet) : 0.f;
        #pragma unroll
        for (int j = 0; j < 7; ++j) {
            float uv = __shfl_sync(0xffffffffu, rv, j);
            ull uv2 = pk2(uv, uv);
            ull t   = f2fma(nai2, si2, uv2);
            ull nsr = f2fma(ar2, sr2, t);
            ull nsi = f2fma(ai2, sr2, f2mul(ar2, si2));
            sr2 = nsr; si2 = nsi;
            ull pr = f2fma(cr2, sr2, f2mul(nci2, si2));
            float px, py; up2(pr, px, py);
            sp[warp][j][lane] = px + py;
        }
        __syncwarp();
        if (lane < 7) {
            float cs = 0.f;
            #pragma unroll
            for (int j = 0; j < 32; ++j) cs += sp[warp][lane][j];  // sum all 32 owners
            yo[l0 + lane] = gelu_tanh(fmaf(Dd, rv, cs));
        }
    }
}

// ---------------- out-proj GEMM + GLU + lazy-BN residual + BN partial sums ----------
__global__ void __launch_bounds__(256) k_gemm(const float* __restrict__ W,
                                              const float* __restrict__ ob,
                                              const float* __restrict__ pg,
                                              const float* __restrict__ pb,
                                              int apply_bn) {
    const int b = blockIdx.z, dt = blockIdx.y, lt = blockIdx.x;
    const int tid = threadIdx.x;
    const int lr = tid & 15, dr = tid >> 4;
    const int d0 = dt * 64, l0 = lt * 64;
    __shared__ float As1[16][64];
    __shared__ float As2[16][64];
    __shared__ float Bs[16][64];
    ull ac1[2][4], ac2[2][4];
    #pragma unroll
    for (int j = 0; j < 2; ++j)
        #pragma unroll
        for (int m = 0; m < 4; ++m) { ac1[j][m] = 0ull; ac2[j][m] = 0ull; }
    const float* Yb = g_y + (size_t)b * DM * LTP;
    for (int kt = 0; kt < 16; ++kt) {
        int k0 = kt * 16;
        __syncthreads();
        #pragma unroll
        for (int r = 0; r < 4; ++r) {
            int idx = tid + r * 256;
            int f = idx >> 6, c = idx & 63;
            As1[f][c] = W[(k0 + f) * 512 + d0 + c];
            As2[f][c] = W[(k0 + f) * 512 + 256 + d0 + c];
            int l = l0 + c;
            Bs[f][c] = (l < LT) ? Yb[(size_t)(k0 + f) * LTP + l] : 0.f;
        }
        __syncthreads();
        #pragma unroll
        for (int kk = 0; kk < 16; ++kk) {
            ulonglong2 a1p = *(const ulonglong2*)&As1[kk][dr * 4];
            ulonglong2 a2p = *(const ulonglong2*)&As2[kk][dr * 4];
            float4 bvv = *(const float4*)&Bs[kk][lr * 4];
            ull bv2[4] = { pk2(bvv.x, bvv.x), pk2(bvv.y, bvv.y),
                           pk2(bvv.z, bvv.z), pk2(bvv.w, bvv.w) };
            #pragma unroll
            for (int m = 0; m < 4; ++m) {
                ac1[0][m] = f2fma(a1p.x, bv2[m], ac1[0][m]);
                ac1[1][m] = f2fma(a1p.y, bv2[m], ac1[1][m]);
                ac2[0][m] = f2fma(a2p.x, bv2[m], ac2[0][m]);
                ac2[1][m] = f2fma(a2p.y, bv2[m], ac2[1][m]);
            }
        }
    }
    // epilogue: glu + lazy-BN residual + stats
    float* Hb = g_h + (size_t)b * DM * LTP;
    float mn[4], sc[4], bt[4], bz1[4], bz2[4];
    #pragma unroll
    for (int jj = 0; jj < 4; ++jj) {
        int d = d0 + dr * 4 + jj;
        bz1[jj] = ob[d]; bz2[jj] = ob[256 + d];
        if (apply_bn) { mn[jj] = g_mean[d]; sc[jj] = g_rstd[d] * pg[d]; bt[jj] = pb[d]; }
        else          { mn[jj] = 0.f; sc[jj] = 1.f; bt[jj] = 0.f; }
    }
    float s[4] = {0.f, 0.f, 0.f, 0.f}, s2[4] = {0.f, 0.f, 0.f, 0.f};
    #pragma unroll
    for (int j2 = 0; j2 < 2; ++j2) {
        #pragma unroll
        for (int m = 0; m < 4; ++m) {
            float z1lo, z1hi, z2lo, z2hi;
            up2(ac1[j2][m], z1lo, z1hi);
            up2(ac2[j2][m], z2lo, z2hi);
            int l = l0 + lr * 4 + m;
            if (l < LT) {
                int jjlo = j2 * 2, jjhi = jjlo + 1;
                int dlo = d0 + dr * 4 + jjlo;
                size_t offlo = (size_t)dlo * LTP + l;
                size_t offhi = offlo + LTP;
                float g_lo = (z1lo + bz1[jjlo]) * sigm(z2lo + bz2[jjlo]);
                float g_hi = (z1hi + bz1[jjhi]) * sigm(z2hi + bz2[jjhi]);
                float hn_lo = fmaf(Hb[offlo] - mn[jjlo], sc[jjlo], bt[jjlo]) + g_lo;
                float hn_hi = fmaf(Hb[offhi] - mn[jjhi], sc[jjhi], bt[jjhi]) + g_hi;
                Hb[offlo] = hn_lo;
                Hb[offhi] = hn_hi;
                s[jjlo] += hn_lo; s2[jjlo] = fmaf(hn_lo, hn_lo, s2[jjlo]);
                s[jjhi] += hn_hi; s2[jjhi] = fmaf(hn_hi, hn_hi, s2[jjhi]);
            }
        }
    }
    #pragma unroll
    for (int o = 8; o; o >>= 1) {
        #pragma unroll
        for (int jj = 0; jj < 4; ++jj) {
            s[jj]  += __shfl_xor_sync(0xffffffffu, s[jj], o);
            s2[jj] += __shfl_xor_sync(0xffffffffu, s2[jj], o);
        }
    }
    if (lr == 0) {
        int slot = lt * 32 + b;
        #pragma unroll
        for (int jj = 0; jj < 4; ++jj) {
            int d = d0 + dr * 4 + jj;
            g_bnp0[d * NT + slot] = s[jj];
            g_bnp1[d * NT + slot] = s2[jj];
        }
    }
}

// ---------------- BN finalize (reduce partials) ----------------
__global__ void k_bnfin() {
    int d = blockIdx.x, tid = threadIdx.x;   // 128 threads
    float s = 0.f, s2 = 0.f;
    for (int i = tid; i < NT; i += 128) {
        s  += g_bnp0[d * NT + i];
        s2 += g_bnp1[d * NT + i];
    }
    __shared__ float sh1[128], sh2[128];
    sh1[tid] = s; sh2[tid] = s2;
    __syncthreads();
    for (int o = 64; o; o >>= 1) {
        if (tid < o) { sh1[tid] += sh1[tid + o]; sh2[tid] += sh2[tid + o]; }
        __syncthreads();
    }
    if (tid == 0) {
        float n = (float)(BB * LT);
        float mean = sh1[0] / n;
        float var = sh2[0] / n - mean * mean;
        g_mean[d] = mean;
        g_rstd[d] = rsqrtf(var + 1e-5f);
    }
}

// ---------------- head (applies final BN lazily) ----------------
__global__ void k_head(const float* __restrict__ W1, const float* __restrict__ b1,
                       const float* __restrict__ W2, const float* __restrict__ b2,
                       const float* __restrict__ pg, const float* __restrict__ pb,
                       float* __restrict__ out) {
    int i = blockIdx.x, b = blockIdx.y, tid = threadIdx.x;  // 128 threads
    int l = (LL - 1) + i;
    float acc = b1[tid];
    const float* Hb = g_h + (size_t)b * DM * LTP + l;
    #pragma unroll 4
    for (int d = 0; d < DM; ++d) {
        float v = fmaf(Hb[(size_t)d * LTP] - g_mean[d], g_rstd[d] * pg[d], pb[d]);
        acc = fmaf(v, W1[d * 128 + tid], acc);
    }
    float sv = acc * sigm(acc);
    __shared__ float sh[128];
    sh[tid] = sv * W2[tid];
    __syncthreads();
    for (int o = 64; o; o >>= 1) {
        if (tid < o) sh[tid] += sh[tid + o];
        __syncthreads();
    }
    if (tid == 0) out[b * HH + i] = sh[0] + b2[0];
}

// ---------------- launch ----------------
extern "C" void kernel_launch(void* const* d_in, const int* in_sizes, int n_in,
                              void* d_out, int out_size) {
    const float* x_past   = (const float*)d_in[0];
    const float* noisy    = (const float*)d_in[1];
    const float* t        = (const float*)d_in[2];
    const float* x_future = (const float*)d_in[3];
    const float* stat     = (const float*)d_in[4];
    const float* freqs    = (const float*)d_in[5];
    const float* phases   = (const float*)d_in[6];
    const float* in_W     = (const float*)d_in[7];
    const float* in_b     = (const float*)d_in[8];
    const float* tm_W1    = (const float*)d_in[9];
    const float* tm_b1    = (const float*)d_in[10];
    const float* tm_W2    = (const float*)d_in[11];
    const float* tm_b2    = (const float*)d_in[12];
    const float* log_dt   = (const float*)d_in[13];
    const float* A_re     = (const float*)d_in[14];
    const float* A_im     = (const float*)d_in[15];
    const float* C_re     = (const float*)d_in[16];
    const float* C_im     = (const float*)d_in[17];
    const float* Dv       = (const float*)d_in[18];
    const float* out_W    = (const float*)d_in[19];
    const float* out_b    = (const float*)d_in[20];
    const float* bn_g     = (const float*)d_in[21];
    const float* bn_b     = (const float*)d_in[22];
    const float* hW1      = (const float*)d_in[23];
    const float* hb1      = (const float*)d_in[24];
    const float* hW2      = (const float*)d_in[25];
    const float* hb2      = (const float*)d_in[26];
    float* out = (float*)d_out;

    k_timemlp<<<BB, 256>>>(t, freqs, phases, tm_W1, tm_b1, tm_W2, tm_b2);
    k_inproj<<<dim3(65, DM / 8, BB), 256>>>(x_past, noisy, x_future, stat, in_W, in_b);

    for (int i = 0; i < NLAYERS; ++i) {
        const float* pg = (i == 0) ? bn_g : bn_g + (i - 1) * DM;
        const float* pb = (i == 0) ? bn_b : bn_b + (i - 1) * DM;
        k_disc<<<DM * DS / 256, 256>>>(log_dt + i * DM, A_re + (size_t)i * DM * DS,
                                       A_im + (size_t)i * DM * DS, C_re + (size_t)i * DM * DS,
                                       C_im + (size_t)i * DM * DS);
        k_scan<<<(BB * DM) / 8, 256>>>(Dv + i * DM, pg, pb, i > 0);
        k_gemm<<<dim3(33, 4, BB), 256>>>(out_W + (size_t)i * DM * 2 * DM,
                                         out_b + i * 2 * DM, pg, pb, i > 0);
        k_bnfin<<<DM, 128>>>();
    }
    k_head<<<dim3(HH, BB), 128>>>(hW1, hb1, hW2, hb2, bn_g + 3 * DM, bn_b + 3 * DM, out);
}

// round 4
// speedup vs baseline: 1.7580x; 1.0085x over previous
#include <cuda_runtime.h>
#include <math.h>

#define BB 32
#define LL 2048
#define HH 8
#define DMET 16
#define SDIM 27
#define DM 256
#define NLAYERS 4
#define DS 64
#define TE 256
#define LT 2055          // LL + HH - 1
#define LTP 2056         // padded row stride
#define FIN 44           // DMET + 1 + SDIM
#define NT 544           // 17 l-tiles * 32 batches (BN partial slots)

typedef unsigned long long ull;

// ---------------- scratch (device globals; no allocation) ----------------
__device__ float g_h[(size_t)BB * DM * LTP];   // activations (pre-BN) [b][d][l]
__device__ float g_y[(size_t)BB * DM * LTP];   // gelu(ssm out)        [b][d][l]
__device__ float g_tb[BB * DM];
__device__ float g_ar[DM * DS], g_ai[DM * DS], g_ckr[DM * DS], g_cki[DM * DS];
__device__ float g_mean[DM], g_rstd[DM];
__device__ float g_bnp0[DM * NT], g_bnp1[DM * NT];

// ---------------- f32x2 packed math ----------------
__device__ __forceinline__ ull pk2(float a, float b) {
    ull r; asm("mov.b64 %0,{%1,%2};" : "=l"(r) : "f"(a), "f"(b)); return r;
}
__device__ __forceinline__ void up2(ull v, float& a, float& b) {
    asm("mov.b64 {%0,%1},%2;" : "=f"(a), "=f"(b) : "l"(v));
}
__device__ __forceinline__ ull f2fma(ull a, ull b, ull c) {
    ull d; asm("fma.rn.f32x2 %0,%1,%2,%3;" : "=l"(d) : "l"(a), "l"(b), "l"(c)); return d;
}
__device__ __forceinline__ ull f2mul(ull a, ull b) {
    ull d; asm("mul.rn.f32x2 %0,%1,%2;" : "=l"(d) : "l"(a), "l"(b)); return d;
}

// ---------------- helpers ----------------
__device__ __forceinline__ float sigm(float x) { return 1.f / (1.f + __expf(-x)); }
__device__ __forceinline__ float gelu_tanh(float v) {
    float v3 = v * v * v;
    float w = 1.5957691216057308f * fmaf(0.044715f, v3, v);
    return v * sigm(w);
}

// ---------------- time MLP ----------------
__global__ void k_timemlp(const float* __restrict__ t, const float* __restrict__ freqs,
                          const float* __restrict__ phases,
                          const float* __restrict__ W1, const float* __restrict__ b1,
                          const float* __restrict__ W2, const float* __restrict__ b2) {
    int b = blockIdx.x, tid = threadIdx.x;
    __shared__ float tf[TE];
    __shared__ float hid[2 * TE];
    float tv = t[b];
    tf[tid] = cosf(fmaf(tv, freqs[tid], phases[tid])) * 1.41421356237309515f;
    __syncthreads();
    for (int j = tid; j < 2 * TE; j += 256) {
        float acc = b1[j];
        #pragma unroll 8
        for (int k = 0; k < TE; ++k) acc = fmaf(tf[k], W1[k * 512 + j], acc);
        hid[j] = acc * sigm(acc);
    }
    __syncthreads();
    float acc = b2[tid];
    #pragma unroll 8
    for (int k = 0; k < 2 * TE; ++k) acc = fmaf(hid[k], W2[k * 256 + tid], acc);
    g_tb[b * DM + tid] = acc;
}

// ---------------- input projection ----------------
__global__ void k_inproj(const float* __restrict__ xp, const float* __restrict__ noisy,
                         const float* __restrict__ xf, const float* __restrict__ sa,
                         const float* __restrict__ inW, const float* __restrict__ inb) {
    int b = blockIdx.z, dt = blockIdx.y, ltile = blockIdx.x;
    int tid = threadIdx.x;
    int ll = tid & 31, dl = tid >> 5;
    int l0 = ltile * 32, d0 = dt * 8;
    __shared__ float sf[32][45];
    __shared__ float sw[FIN][8];
    for (int i = tid; i < 32 * FIN; i += 256) {
        int li = i / FIN, f = i % FIN;
        int l = l0 + li;
        float v = 0.f;
        if (l < LT) {
            if (f < DMET)
                v = (l < LL) ? xp[((size_t)b * LL + l) * DMET + f]
                             : xf[((size_t)b * (HH - 1) + (l - LL)) * DMET + f];
            else if (f == DMET)
                v = (l >= LL - 1) ? noisy[b * HH + (l - (LL - 1))] : 0.f;
            else
                v = sa[b * SDIM + (f - DMET - 1)];
        }
        sf[li][f] = v;
    }
    for (int i = tid; i < FIN * 8; i += 256) {
        int f = i >> 3, c = i & 7;
        sw[f][c] = inW[f * DM + d0 + c];
    }
    __syncthreads();
    int l = l0 + ll, d = d0 + dl;
    float acc = inb[d];
    #pragma unroll
    for (int f = 0; f < FIN; ++f) acc = fmaf(sf[ll][f], sw[f][dl], acc);
    if (l >= LL - 1) acc += g_tb[b * DM + d];
    if (l < LT) g_h[((size_t)b * DM + d) * LTP + l] = acc;
}

// ---------------- per-layer discretization ----------------
__global__ void k_disc(const float* __restrict__ log_dt, const float* __restrict__ Are,
                       const float* __restrict__ Aim, const float* __restrict__ Cre,
                       const float* __restrict__ Cim) {
    int idx = blockIdx.x * 256 + threadIdx.x;
    int d = idx >> 6;
    float dt = expf(log_dt[d]);
    float ar_ = Are[idx], ai_ = Aim[idx];
    float xr = dt * ar_, xi = dt * ai_;
    float mag = expf(xr);
    float cs = cosf(xi), sn = sinf(xi);
    float a_r = mag * cs, a_i = mag * sn;
    float em = expm1f(xr);
    float er = fmaf(em, cs, cs - 1.f);
    float ei = a_i;
    float inv = 1.f / fmaf(ar_, ar_, ai_ * ai_);
    float qr = fmaf(er, ar_, ei * ai_) * inv;
    float qi = fmaf(ei, ar_, -er * ai_) * inv;
    float cr = Cre[idx], ci = Cim[idx];
    g_ckr[idx] = 2.f * fmaf(cr, qr, -ci * qi);
    g_cki[idx] = 2.f * fmaf(cr, qi, ci * qr);
    g_ar[idx] = a_r;
    g_ai[idx] = a_i;
}

// ---------------- SSM scan: warp per (b,d), f32x2 states, smem transpose reduce ------
__global__ void __launch_bounds__(256) k_scan(const float* __restrict__ Dv,
                                              const float* __restrict__ pg,
                                              const float* __restrict__ pb,
                                              int apply_bn) {
    __shared__ float sp[8][32][33];
    int warp = threadIdx.x >> 5, lane = threadIdx.x & 31;
    int wid = blockIdx.x * 8 + warp;
    int b = wid >> 8, d = wid & 255;
    float mean = 0.f, scl = 1.f, bet = 0.f;
    if (apply_bn) { mean = g_mean[d]; scl = g_rstd[d] * pg[d]; bet = pb[d]; }
    int i0 = d * DS + lane, i1 = i0 + 32;
    ull ar2  = pk2(g_ar[i0],  g_ar[i1]);
    ull ai2  = pk2(g_ai[i0],  g_ai[i1]);
    ull nai2 = pk2(-g_ai[i0], -g_ai[i1]);
    ull cr2  = pk2(g_ckr[i0], g_ckr[i1]);
    ull nci2 = pk2(-g_cki[i0], -g_cki[i1]);
    ull sr2 = 0ull, si2 = 0ull;
    float Dd = Dv[d];
    const float* u = g_h + ((size_t)b * DM + d) * LTP;
    float* yo = g_y + ((size_t)b * DM + d) * LTP;

    for (int l0 = 0; l0 < 2048; l0 += 32) {
        float rv = u[l0 + lane];
        rv = fmaf(rv - mean, scl, bet);
        #pragma unroll
        for (int j = 0; j < 32; ++j) {
            float uv = __shfl_sync(0xffffffffu, rv, j);
            ull uv2 = pk2(uv, uv);
            ull t   = f2fma(nai2, si2, uv2);
            ull nsr = f2fma(ar2, sr2, t);
            ull nsi = f2fma(ai2, sr2, f2mul(ar2, si2));
            sr2 = nsr; si2 = nsi;
            ull pr = f2fma(cr2, sr2, f2mul(nci2, si2));
            float px, py; up2(pr, px, py);
            sp[warp][j][lane] = px + py;   // [step][owner]
        }
        __syncwarp();
        float cs = 0.f;
        #pragma unroll
        for (int j = 0; j < 32; ++j) cs += sp[warp][lane][j];
        yo[l0 + lane] = gelu_tanh(fmaf(Dd, rv, cs));
        __syncwarp();
    }
    // tail: 7 steps
    {
        const int l0 = 2048;
        float rv = (lane < 7) ? fmaf(u[l0 + lane] - mean, scl, bet) : 0.f;
        #pragma unroll
        for (int j = 0; j < 7; ++j) {
            float uv = __shfl_sync(0xffffffffu, rv, j);
            ull uv2 = pk2(uv, uv);
            ull t   = f2fma(nai2, si2, uv2);
            ull nsr = f2fma(ar2, sr2, t);
            ull nsi = f2fma(ai2, sr2, f2mul(ar2, si2));
            sr2 = nsr; si2 = nsi;
            ull pr = f2fma(cr2, sr2, f2mul(nci2, si2));
            float px, py; up2(pr, px, py);
            sp[warp][j][lane] = px + py;
        }
        __syncwarp();
        if (lane < 7) {
            float cs = 0.f;
            #pragma unroll
            for (int j = 0; j < 32; ++j) cs += sp[warp][lane][j];
            yo[l0 + lane] = gelu_tanh(fmaf(Dd, rv, cs));
        }
    }
}

// ---- out-proj GEMM (64d x 128l tile, f32x2 packed along l) + GLU + lazy-BN ----------
__global__ void __launch_bounds__(256) k_gemm(const float* __restrict__ W,
                                              const float* __restrict__ ob,
                                              const float* __restrict__ pg,
                                              const float* __restrict__ pb,
                                              int apply_bn) {
    const int b = blockIdx.z, dt = blockIdx.y, lt = blockIdx.x;
    const int tid = threadIdx.x;
    const int lr = tid & 15, dr = tid >> 4;      // lr: 8-l group, dr: 4-d group
    const int d0 = dt * 64, l0 = lt * 128;
    __shared__ float As1[16][64];
    __shared__ float As2[16][64];
    __shared__ float Bs[16][128];
    ull ac1[4][4], ac2[4][4];
    #pragma unroll
    for (int j = 0; j < 4; ++j)
        #pragma unroll
        for (int m = 0; m < 4; ++m) { ac1[j][m] = 0ull; ac2[j][m] = 0ull; }

    const float* Yb = g_y + (size_t)b * DM * LTP;
    const int lf = tid >> 4;            // load row (0..15)
    const int la = (tid & 15) * 4;      // A col
    const int lb = (tid & 15) * 8;      // B col

    // prefetch kt = 0
    float4 pA1, pA2, pB0, pB1;
    {
        const float* wr = W + lf * 512 + d0;
        pA1 = *(const float4*)(wr + la);
        pA2 = *(const float4*)(wr + 256 + la);
        const float* yr = Yb + (size_t)lf * LTP + l0 + lb;
        if (l0 + lb + 7 < LT) {
            pB0 = *(const float4*)yr;
            pB1 = *(const float4*)(yr + 4);
        } else {
            float v[8];
            #pragma unroll
            for (int e = 0; e < 8; ++e) v[e] = (l0 + lb + e < LT) ? yr[e] : 0.f;
            pB0 = make_float4(v[0], v[1], v[2], v[3]);
            pB1 = make_float4(v[4], v[5], v[6], v[7]);
        }
    }

    for (int kt = 0; kt < 16; ++kt) {
        __syncthreads();
        *(float4*)&As1[lf][la] = pA1;
        *(float4*)&As2[lf][la] = pA2;
        *(float4*)&Bs[lf][lb]     = pB0;
        *(float4*)&Bs[lf][lb + 4] = pB1;
        __syncthreads();
        if (kt < 15) {
            int k0 = (kt + 1) * 16;
            const float* wr = W + (k0 + lf) * 512 + d0;
            pA1 = *(const float4*)(wr + la);
            pA2 = *(const float4*)(wr + 256 + la);
            const float* yr = Yb + (size_t)(k0 + lf) * LTP + l0 + lb;
            if (l0 + lb + 7 < LT) {
                pB0 = *(const float4*)yr;
                pB1 = *(const float4*)(yr + 4);
            } else {
                float v[8];
                #pragma unroll
                for (int e = 0; e < 8; ++e) v[e] = (l0 + lb + e < LT) ? yr[e] : 0.f;
                pB0 = make_float4(v[0], v[1], v[2], v[3]);
                pB1 = make_float4(v[4], v[5], v[6], v[7]);
            }
        }
        #pragma unroll
        for (int kk = 0; kk < 16; ++kk) {
            float4 a1 = *(const float4*)&As1[kk][dr * 4];   // warp-broadcast
            float4 a2 = *(const float4*)&As2[kk][dr * 4];
            ulonglong2 b01 = *(const ulonglong2*)&Bs[kk][lr * 8];
            ulonglong2 b23 = *(const ulonglong2*)&Bs[kk][lr * 8 + 4];
            ull bp[4] = { b01.x, b01.y, b23.x, b23.y };
            ull a1d[4] = { pk2(a1.x, a1.x), pk2(a1.y, a1.y), pk2(a1.z, a1.z), pk2(a1.w, a1.w) };
            ull a2d[4] = { pk2(a2.x, a2.x), pk2(a2.y, a2.y), pk2(a2.z, a2.z), pk2(a2.w, a2.w) };
            #pragma unroll
            for (int j = 0; j < 4; ++j)
                #pragma unroll
                for (int m = 0; m < 4; ++m) {
                    ac1[j][m] = f2fma(a1d[j], bp[m], ac1[j][m]);
                    ac2[j][m] = f2fma(a2d[j], bp[m], ac2[j][m]);
                }
        }
    }

    // epilogue: glu + lazy-BN residual + stats (8 contiguous l per thread per d)
    float* Hb = g_h + (size_t)b * DM * LTP;
    const int lbase = l0 + lr * 8;
    float s[4], s2[4];
    #pragma unroll
    for (int j = 0; j < 4; ++j) { s[j] = 0.f; s2[j] = 0.f; }
    #pragma unroll
    for (int j = 0; j < 4; ++j) {
        int d = d0 + dr * 4 + j;
        float bz1 = ob[d], bz2 = ob[256 + d];
        float mn = 0.f, sc = 1.f, bt = 0.f;
        if (apply_bn) { mn = g_mean[d]; sc = g_rstd[d] * pg[d]; bt = pb[d]; }
        float* hrow = Hb + (size_t)d * LTP + lbase;
        float hv[8];
        bool full = (lbase + 7 < LT);
        if (full) {
            float4 t0 = *(const float4*)hrow;
            float4 t1 = *(const float4*)(hrow + 4);
            hv[0]=t0.x; hv[1]=t0.y; hv[2]=t0.z; hv[3]=t0.w;
            hv[4]=t1.x; hv[5]=t1.y; hv[6]=t1.z; hv[7]=t1.w;
        } else {
            #pragma unroll
            for (int e = 0; e < 8; ++e) hv[e] = (lbase + e < LT) ? hrow[e] : 0.f;
        }
        float hn[8];
        #pragma unroll
        for (int m = 0; m < 4; ++m) {
            float z1a, z1b, z2a, z2b;
            up2(ac1[j][m], z1a, z1b);
            up2(ac2[j][m], z2a, z2b);
            float ga = (z1a + bz1) * sigm(z2a + bz2);
            float gb = (z1b + bz1) * sigm(z2b + bz2);
            hn[2*m]   = fmaf(hv[2*m]   - mn, sc, bt) + ga;
            hn[2*m+1] = fmaf(hv[2*m+1] - mn, sc, bt) + gb;
        }
        if (full) {
            *(float4*)hrow       = make_float4(hn[0], hn[1], hn[2], hn[3]);
            *(float4*)(hrow + 4) = make_float4(hn[4], hn[5], hn[6], hn[7]);
            #pragma unroll
            for (int e = 0; e < 8; ++e) { s[j] += hn[e]; s2[j] = fmaf(hn[e], hn[e], s2[j]); }
        } else {
            #pragma unroll
            for (int e = 0; e < 8; ++e)
                if (lbase + e < LT) {
                    hrow[e] = hn[e];
                    s[j] += hn[e]; s2[j] = fmaf(hn[e], hn[e], s2[j]);
                }
        }
    }
    // reduce over the 16 lr lanes (stays within warp half)
    #pragma unroll
    for (int o = 8; o; o >>= 1) {
        #pragma unroll
        for (int j = 0; j < 4; ++j) {
            s[j]  += __shfl_xor_sync(0xffffffffu, s[j], o);
            s2[j] += __shfl_xor_sync(0xffffffffu, s2[j], o);
        }
    }
    if (lr == 0) {
        int slot = lt * 32 + b;
        #pragma unroll
        for (int j = 0; j < 4; ++j) {
            int d = d0 + dr * 4 + j;
            g_bnp0[d * NT + slot] = s[j];
            g_bnp1[d * NT + slot] = s2[j];
        }
    }
}

// ---------------- BN finalize (reduce partials) ----------------
__global__ void k_bnfin() {
    int d = blockIdx.x, tid = threadIdx.x;   // 128 threads
    float s = 0.f, s2 = 0.f;
    for (int i = tid; i < NT; i += 128) {
        s  += g_bnp0[d * NT + i];
        s2 += g_bnp1[d * NT + i];
    }
    __shared__ float sh1[128], sh2[128];
    sh1[tid] = s; sh2[tid] = s2;
    __syncthreads();
    for (int o = 64; o; o >>= 1) {
        if (tid < o) { sh1[tid] += sh1[tid + o]; sh2[tid] += sh2[tid + o]; }
        __syncthreads();
    }
    if (tid == 0) {
        float n = (float)(BB * LT);
        float mean = sh1[0] / n;
        float var = sh2[0] / n - mean * mean;
        g_mean[d] = mean;
        g_rstd[d] = rsqrtf(var + 1e-5f);
    }
}

// ---------------- head (applies final BN lazily) ----------------
__global__ void k_head(const float* __restrict__ W1, const float* __restrict__ b1,
                       const float* __restrict__ W2, const float* __restrict__ b2,
                       const float* __restrict__ pg, const float* __restrict__ pb,
                       float* __restrict__ out) {
    int i = blockIdx.x, b = blockIdx.y, tid = threadIdx.x;  // 128 threads
    int l = (LL - 1) + i;
    float acc = b1[tid];
    const float* Hb = g_h + (size_t)b * DM * LTP + l;
    #pragma unroll 4
    for (int d = 0; d < DM; ++d) {
        float v = fmaf(Hb[(size_t)d * LTP] - g_mean[d], g_rstd[d] * pg[d], pb[d]);
        acc = fmaf(v, W1[d * 128 + tid], acc);
    }
    float sv = acc * sigm(acc);
    __shared__ float sh[128];
    sh[tid] = sv * W2[tid];
    __syncthreads();
    for (int o = 64; o; o >>= 1) {
        if (tid < o) sh[tid] += sh[tid + o];
        __syncthreads();
    }
    if (tid == 0) out[b * HH + i] = sh[0] + b2[0];
}

// ---------------- launch ----------------
extern "C" void kernel_launch(void* const* d_in, const int* in_sizes, int n_in,
                              void* d_out, int out_size) {
    const float* x_past   = (const float*)d_in[0];
    const float* noisy    = (const float*)d_in[1];
    const float* t        = (const float*)d_in[2];
    const float* x_future = (const float*)d_in[3];
    const float* stat     = (const float*)d_in[4];
    const float* freqs    = (const float*)d_in[5];
    const float* phases   = (const float*)d_in[6];
    const float* in_W     = (const float*)d_in[7];
    const float* in_b     = (const float*)d_in[8];
    const float* tm_W1    = (const float*)d_in[9];
    const float* tm_b1    = (const float*)d_in[10];
    const float* tm_W2    = (const float*)d_in[11];
    const float* tm_b2    = (const float*)d_in[12];
    const float* log_dt   = (const float*)d_in[13];
    const float* A_re     = (const float*)d_in[14];
    const float* A_im     = (const float*)d_in[15];
    const float* C_re     = (const float*)d_in[16];
    const float* C_im     = (const float*)d_in[17];
    const float* Dv       = (const float*)d_in[18];
    const float* out_W    = (const float*)d_in[19];
    const float* out_b    = (const float*)d_in[20];
    const float* bn_g     = (const float*)d_in[21];
    const float* bn_b     = (const float*)d_in[22];
    const float* hW1      = (const float*)d_in[23];
    const float* hb1      = (const float*)d_in[24];
    const float* hW2      = (const float*)d_in[25];
    const float* hb2      = (const float*)d_in[26];
    float* out = (float*)d_out;

    k_timemlp<<<BB, 256>>>(t, freqs, phases, tm_W1, tm_b1, tm_W2, tm_b2);
    k_inproj<<<dim3(65, DM / 8, BB), 256>>>(x_past, noisy, x_future, stat, in_W, in_b);

    for (int i = 0; i < NLAYERS; ++i) {
        const float* pg = (i == 0) ? bn_g : bn_g + (i - 1) * DM;
        const float* pb = (i == 0) ? bn_b : bn_b + (i - 1) * DM;
        k_disc<<<DM * DS / 256, 256>>>(log_dt + i * DM, A_re + (size_t)i * DM * DS,
                                       A_im + (size_t)i * DM * DS, C_re + (size_t)i * DM * DS,
                                       C_im + (size_t)i * DM * DS);
        k_scan<<<(BB * DM) / 8, 256>>>(Dv + i * DM, pg, pb, i > 0);
        k_gemm<<<dim3(17, 4, BB), 256>>>(out_W + (size_t)i * DM * 2 * DM,
                                         out_b + i * 2 * DM, pg, pb, i > 0);
        k_bnfin<<<DM, 128>>>();
    }
    k_head<<<dim3(HH, BB), 128>>>(hW1, hb1, hW2, hb2, bn_g + 3 * DM, bn_b + 3 * DM, out);
}